// round 11
// baseline (speedup 1.0000x reference)
#include <cuda_runtime.h>
#include <cuda_fp16.h>
#include <math.h>
#include <stdint.h>

// ---------------- problem constants ----------------
#define VOCAB   8192
#define DIM     512
#define M_ROWS  32768          // 8*4096
#define MOM     0.995f
// output packing (flat f32, tuple order): x_q | loss | perplexity | new_dict | new_counts
#define OFF_LOSS 16777216ull
#define OFF_PERP 16777217ull
#define OFF_DICT 16777218ull
#define OFF_CNT  20971522ull   // OFF_DICT + VOCAB*DIM

// ---------------- GEMM tiling (pass 1, fp16-hi approx) ----------------
#define TM      128
#define TN      256
#define KC      32             // floats per K chunk
#define NCHUNK  (DIM / KC)     // 16
#define NTPC    8              // nt tiles per CTA (persistent sweep)
#define TTOT    (NTPC * NCHUNK) // 128 flattened chunk steps
#define MARGIN  0.02f          // >= 3x fully-aligned worst-case fp16 rounding error
#define CAP     16777216       // candidate capacity
// smem layout: A full tile 128KB | B 3x16KB | h_s 2x1KB | sbest 1KB
#define A_OFF    0
#define B_OFF    131072
#define B_STAGE  16384
#define SM_H     180224
#define SM_BEST  182272
#define SM_TOTAL 183296

// ---------------- device scratch (static; no allocations) ----------------
__device__ float               g_e[VOCAB * DIM];
__device__ float               g_h[VOCAB];          // 0.5*||e||^2
__device__ unsigned long long  g_best[M_ROWS];      // approx (pass-1) packed keys
__device__ unsigned long long  g_best2[M_ROWS];     // exact (pass-2) packed keys
__device__ float               g_cnt[VOCAB];
__device__ double              g_loss;
__device__ unsigned int        g_ncand;
__device__ uint32_t            g_cand[CAP];         // row*8192+col
// fragment-packed fp16 hi-limb operands
__device__ uint32_t            g_xh[M_ROWS * DIM / 2];   // 32MB
__device__ uint32_t            g_eh[VOCAB  * DIM / 2];   // 8MB

// ---------------- helpers ----------------
__device__ __forceinline__ uint32_t smem_u32(const void* p) {
    uint32_t a;
    asm("{ .reg .u64 t; cvta.to.shared.u64 t, %1; cvt.u32.u64 %0, t; }" : "=r"(a) : "l"(p));
    return a;
}
__device__ __forceinline__ void cp16(uint32_t dst, const void* src) {
    asm volatile("cp.async.ca.shared.global [%0], [%1], 16;" :: "r"(dst), "l"(src));
}
#define CP_COMMIT() asm volatile("cp.async.commit_group;")
#define CP_WAIT(n)  asm volatile("cp.async.wait_group %0;" :: "n"(n))

#define MMA16(d, a0, a1, a2, a3, b0, b1)                                      \
    asm volatile(                                                             \
        "mma.sync.aligned.m16n8k16.row.col.f32.f16.f16.f32 "                  \
        "{%0,%1,%2,%3}, {%4,%5,%6,%7}, {%8,%9}, {%0,%1,%2,%3};"               \
        : "+f"(d[0]), "+f"(d[1]), "+f"(d[2]), "+f"(d[3])                      \
        : "r"(a0), "r"(a1), "r"(a2), "r"(a3), "r"(b0), "r"(b1))

__device__ __forceinline__ unsigned int fkey(float s) {
    unsigned int ub = __float_as_uint(s);
    return (ub & 0x80000000u) ? ~ub : (ub | 0x80000000u);
}
__device__ __forceinline__ float keyscore(unsigned long long k) {
    unsigned int ub = (unsigned int)(k >> 32);
    unsigned int orig = (ub & 0x80000000u) ? (ub & 0x7fffffffu) : ~ub;
    return __uint_as_float(orig);   // k==0 -> -NaN; callers use fmaxf
}
__device__ __forceinline__ uint32_t pack_h2(float v0, float v1) {
    __half2 p = __halves2half2(__float2half_rn(v0), __float2half_rn(v1));
    return *(uint32_t*)&p;
}

// ---------------- kernel A: codewords + half squared norms ----------------
__global__ void compute_codewords(const float* __restrict__ dict,
                                  const float* __restrict__ counts) {
    int k = blockIdx.x;
    int t = threadIdx.x;
    float inv = 1.0f / counts[k];
    const float4* src = (const float4*)(dict + (size_t)k * DIM);
    float4*       dst = (float4*)(g_e + (size_t)k * DIM);
    float4 v = src[t];
    v.x *= inv; v.y *= inv; v.z *= inv; v.w *= inv;
    dst[t] = v;
    float s = v.x * v.x + v.y * v.y + v.z * v.z + v.w * v.w;
    #pragma unroll
    for (int o = 16; o; o >>= 1) s += __shfl_xor_sync(0xffffffffu, s, o);
    __shared__ float ws[4];
    if ((t & 31) == 0) ws[t >> 5] = s;
    __syncthreads();
    if (t == 0) g_h[k] = 0.5f * (ws[0] + ws[1] + ws[2] + ws[3]);
}

// ---------------- pack X / E into fragment-ordered fp16 hi limbs ----------------
// A u32 index: [mt(256)][c(16)][msub(8)][ks(2)][lane(32)][reg(4)]
__global__ void split_x(const float* __restrict__ X) {
    int o = blockIdx.x * 256 + threadIdx.x;       // 8388608 total
    int reg  =  o        & 3;
    int lane = (o >> 2)  & 31;
    int ks   = (o >> 7)  & 1;
    int msub = (o >> 8)  & 7;
    int c    = (o >> 11) & 15;
    int mt   =  o >> 15;
    int m = mt * 128 + msub * 16 + (lane >> 2) + (reg & 1) * 8;
    int k = c * 32 + ks * 16 + (lane & 3) * 2 + (reg >> 1) * 8;
    const float* xp = X + (size_t)m * DIM + k;
    g_xh[o] = pack_h2(xp[0], xp[1]);
}

// B u32 index: [nt(32)][c(16)][nsub(32)][ks(2)][lane(32)][reg(2)]
__global__ void split_e() {
    int o = blockIdx.x * 256 + threadIdx.x;       // 2097152 total
    int reg  =  o        & 1;
    int lane = (o >> 1)  & 31;
    int ks   = (o >> 6)  & 1;
    int nsub = (o >> 7)  & 31;
    int c    = (o >> 12) & 15;
    int nt   =  o >> 16;
    int n = nt * 256 + nsub * 8 + (lane >> 2);
    int k = c * 32 + ks * 16 + (lane & 3) * 2 + reg * 8;
    const float* ep = g_e + (size_t)n * DIM + k;
    g_eh[o] = pack_h2(ep[0], ep[1]);
}

// ---------------- kernel B: init scratch + new_dict = 0.995*dict ----------------
__global__ void init_kernel(const float* __restrict__ dict, float* __restrict__ out) {
    size_t i = (size_t)blockIdx.x * blockDim.x + threadIdx.x;
    size_t stride = (size_t)gridDim.x * blockDim.x;
    const size_t nd2 = (size_t)VOCAB * DIM / 2;
    float2* od = (float2*)(out + OFF_DICT);
    const float2* dd = (const float2*)dict;
    for (size_t j = i; j < nd2; j += stride) {
        float2 d = dd[j];
        d.x *= MOM; d.y *= MOM;
        od[j] = d;
    }
    for (size_t j = i; j < M_ROWS; j += stride) { g_best[j] = 0ull; g_best2[j] = 0ull; }
    for (size_t j = i; j < VOCAB;  j += stride) g_cnt[j] = 0.0f;
    if (i == 0) { g_loss = 0.0; g_ncand = 0u; }
}

// ---------------- kernel C: persistent-mt fp16-hi GEMM + candidate harvest ----------------
__global__ void __launch_bounds__(512, 1)
gemm_approx() {
    extern __shared__ char sm[];
    uint32_t smb = smem_u32(sm);
    float* h_s = (float*)(sm + SM_H);                       // [2][256]
    unsigned long long* sbest = (unsigned long long*)(sm + SM_BEST);
    const int tid = threadIdx.x, lane = tid & 31, w = tid >> 5;
    const int wm = w >> 3, wn = w & 7;           // 2 x 8 warps, warp tile 64x32
    const int mt = blockIdx.x, ng = blockIdx.y;  // 256 mt x 4 nt-groups

    if (tid < TM) sbest[tid] = 0ull;

    const uint32_t* gA = g_xh + (size_t)(mt * NCHUNK) * 2048;

    // prologue: load full A tile (128KB) once
    #pragma unroll
    for (int i = 0; i < 16; i++)
        cp16(smb + A_OFF + i * 8192 + tid * 16, gA + i * 2048 + tid * 4);
    CP_COMMIT();

    auto issueB = [&](int t) {
        int ntg = ng * NTPC + (t >> 4);
        int c = t & 15;
        const uint32_t* b = g_eh + (size_t)(ntg * NCHUNK) * 4096 + c * 4096;
        uint32_t sb = smb + B_OFF + (uint32_t)(t % 3) * B_STAGE;
        cp16(sb + tid * 16, b + tid * 4);
        cp16(sb + 8192 + tid * 16, b + 2048 + tid * 4);
        CP_COMMIT();
    };

    issueB(0); issueB(1);

    float acc[4][4][4];
    #pragma unroll
    for (int i = 0; i < 4; i++)
        #pragma unroll
        for (int j = 0; j < 4; j++)
            #pragma unroll
            for (int r = 0; r < 4; r++) acc[i][j][r] = 0.0f;

    for (int t = 0; t < TTOT; t++) {
        if (t == TTOT - 1) CP_WAIT(0);
        else               CP_WAIT(1);
        __syncthreads();                    // chunk t ready; all reads of t-1 done
        if (t + 2 < TTOT) issueB(t + 2);    // stage (t+2)%3: disjoint from t, t+1

        if ((t & 15) == 0) {                // stage h for this nt (used 15 steps later)
            int ntg = ng * NTPC + (t >> 4);
            int hb = ((t >> 4) & 1) * 256;
            for (int i = tid; i < TN; i += 512) h_s[hb + i] = g_h[ntg * TN + i];
        }

        int sbase = B_OFF + (t % 3) * B_STAGE;
        int abase = A_OFF + (t & 15) * 8192;
        #pragma unroll
        for (int ks = 0; ks < 2; ks++) {
            uint2 bf[4];
            #pragma unroll
            for (int j = 0; j < 4; j++)
                bf[j] = *(const uint2*)(sm + sbase +
                                        (wn * 4 + j) * 512 + ks * 256 + lane * 8);
            uint4 af[4];
            #pragma unroll
            for (int i = 0; i < 4; i++)
                af[i] = *(const uint4*)(sm + abase +
                                        (wm * 4 + i) * 1024 + ks * 512 + lane * 16);
            #pragma unroll
            for (int i = 0; i < 4; i++)
                #pragma unroll
                for (int j = 0; j < 4; j++)
                    MMA16(acc[i][j], af[i].x, af[i].y, af[i].z, af[i].w, bf[j].x, bf[j].y);
        }

        if ((t & 15) == 15) {
            // ---- epilogue for tile ntg: local best (accumulated), harvest, reset ----
            int ntg = ng * NTPC + (t >> 4);
            int hb = ((t >> 4) & 1) * 256;
            __syncthreads();                // MMA accs final; also guards sbest epoch
            #pragma unroll
            for (int i = 0; i < 4; i++) {
                #pragma unroll
                for (int half = 0; half < 2; half++) {
                    int rowl = wm * 64 + i * 16 + (lane >> 2) + half * 8;
                    float bs = -1e30f; int bc = 0;
                    #pragma unroll
                    for (int j = 0; j < 4; j++)
                        #pragma unroll
                        for (int p = 0; p < 2; p++) {
                            int coll = wn * 32 + j * 8 + (lane & 3) * 2 + p;
                            float s = acc[i][j][half * 2 + p] - h_s[hb + coll];
                            int col = ntg * TN + coll;
                            if (s > bs || (s == bs && col < bc)) { bs = s; bc = col; }
                        }
                    unsigned long long key =
                        ((unsigned long long)fkey(bs) << 32) | (unsigned int)(VOCAB - 1 - bc);
                    #pragma unroll
                    for (int off = 1; off < 4; off <<= 1) {
                        unsigned long long other = __shfl_xor_sync(0xffffffffu, key, off);
                        if (other > key) key = other;
                    }
                    if ((lane & 3) == 0) atomicMax(&sbest[rowl], key);
                }
            }
            __syncthreads();
            #pragma unroll
            for (int i = 0; i < 4; i++) {
                #pragma unroll
                for (int half = 0; half < 2; half++) {
                    int rowl = wm * 64 + i * 16 + (lane >> 2) + half * 8;
                    int rowg = mt * TM + rowl;
                    float tb = keyscore(sbest[rowl]);       // accumulated over sweep
                    float gb = keyscore(g_best[rowg]);      // racy lower bound: safe
                    float thr = fmaxf(tb, gb) - MARGIN;
                    #pragma unroll
                    for (int j = 0; j < 4; j++)
                        #pragma unroll
                        for (int p = 0; p < 2; p++) {
                            int coll = wn * 32 + j * 8 + (lane & 3) * 2 + p;
                            float s = acc[i][j][half * 2 + p] - h_s[hb + coll];
                            bool pred = (s >= thr);
                            unsigned int m = __ballot_sync(0xffffffffu, pred);
                            if (m) {
                                int leader = __ffs(m) - 1;
                                unsigned int base = 0;
                                if (lane == leader)
                                    base = atomicAdd(&g_ncand, (unsigned)__popc(m));
                                base = __shfl_sync(0xffffffffu, base, leader);
                                if (pred) {
                                    unsigned int idx = base + __popc(m & ((1u << lane) - 1));
                                    if (idx < CAP)
                                        g_cand[idx] = (unsigned)rowg * 8192u
                                                    + (unsigned)(ntg * TN + coll);
                                }
                            }
                        }
                }
            }
            #pragma unroll
            for (int i = 0; i < 4; i++)
                #pragma unroll
                for (int j = 0; j < 4; j++)
                    #pragma unroll
                    for (int r = 0; r < 4; r++) acc[i][j][r] = 0.0f;
        }
    }
    __syncthreads();
    if (tid < TM) atomicMax(&g_best[(size_t)mt * TM + tid], sbest[tid]);
}

// ---------------- kernel C2: exact fp32 rescore of candidates ----------------
__global__ void rescore(const float* __restrict__ X) {
    int gw   = ((int)blockIdx.x * blockDim.x + threadIdx.x) >> 5;
    int nw   = (gridDim.x * blockDim.x) >> 5;
    int lane = threadIdx.x & 31;
    unsigned int n = g_ncand;
    if (n > CAP) n = CAP;
    for (unsigned int c = gw; c < n; c += nw) {
        uint32_t rc = g_cand[c];
        int row = rc >> 13, col = rc & 8191;
        const float4* xr = (const float4*)(X + (size_t)row * DIM);
        const float4* er = (const float4*)(g_e + (size_t)col * DIM);
        float s = 0.0f;
        #pragma unroll
        for (int t = lane; t < DIM / 4; t += 32) {
            float4 x = xr[t], e = er[t];
            s += x.x * e.x + x.y * e.y + x.z * e.z + x.w * e.w;
        }
        #pragma unroll
        for (int o = 16; o; o >>= 1) s += __shfl_xor_sync(0xffffffffu, s, o);
        if (lane == 0) {
            float sc = s - g_h[col];
            unsigned long long key =
                ((unsigned long long)fkey(sc) << 32) | (unsigned int)(VOCAB - 1 - col);
            atomicMax(&g_best2[row], key);
        }
    }
}

// ---------------- kernel D: gather x_q, loss, histogram, scatter x_sum ----------------
__global__ void scatter_kernel(const float* __restrict__ X, float* __restrict__ out) {
    int gw   = ((int)blockIdx.x * blockDim.x + threadIdx.x) >> 5;  // row
    int lane = threadIdx.x & 31;
    __shared__ double lred[8];
    double lsum = 0.0;
    if (gw < M_ROWS) {
        unsigned long long key = g_best2[gw];
        int k = VOCAB - 1 - (int)(key & 0xffffffffu);
        const float4* e4 = (const float4*)(g_e + (size_t)k * DIM);
        const float4* x4 = (const float4*)(X + (size_t)gw * DIM);
        float4*       q4 = (float4*)(out + (size_t)gw * DIM);
        float* nd = out + OFF_DICT + (size_t)k * DIM;
        float fs = 0.0f;
        #pragma unroll
        for (int c = lane; c < DIM / 4; c += 32) {
            float4 e = e4[c], x = x4[c];
            q4[c] = e;
            float dx = e.x - x.x, dy = e.y - x.y, dz = e.z - x.z, dw = e.w - x.w;
            fs += dx * dx + dy * dy + dz * dz + dw * dw;
            atomicAdd(nd + c * 4 + 0, x.x);
            atomicAdd(nd + c * 4 + 1, x.y);
            atomicAdd(nd + c * 4 + 2, x.z);
            atomicAdd(nd + c * 4 + 3, x.w);
        }
        #pragma unroll
        for (int o = 16; o; o >>= 1) fs += __shfl_xor_sync(0xffffffffu, fs, o);
        if (lane == 0) {
            atomicAdd(&g_cnt[k], 1.0f);
            lsum = (double)fs;
        }
    }
    int wid = threadIdx.x >> 5;
    if (lane == 0) lred[wid] = lsum;
    __syncthreads();
    if (threadIdx.x == 0) {
        double t = 0.0;
        for (int i = 0; i < 8; i++) t += lred[i];
        atomicAdd(&g_loss, t);
    }
}

// ---------------- kernel E: new_counts, loss, perplexity ----------------
__global__ void finalize_kernel(const float* __restrict__ counts, float* __restrict__ out) {
    __shared__ double red[32];
    __shared__ double s_total;
    int tid = threadIdx.x;
    double s = 0.0;
    for (int k = tid; k < VOCAB; k += 1024) {
        float nc = counts[k] * MOM + g_cnt[k];
        out[OFF_CNT + k] = nc;
        s += (double)nc;
    }
    #pragma unroll
    for (int o = 16; o; o >>= 1) s += __shfl_xor_sync(0xffffffffu, s, o);
    if ((tid & 31) == 0) red[tid >> 5] = s;
    __syncthreads();
    if (tid < 32) {
        double t = red[tid];
        #pragma unroll
        for (int o = 16; o; o >>= 1) t += __shfl_xor_sync(0xffffffffu, t, o);
        if (tid == 0) s_total = t;
    }
    __syncthreads();
    double total = s_total;
    double h = 0.0;
    for (int k = tid; k < VOCAB; k += 1024) {
        double p = (double)out[OFF_CNT + k] / total;
        h += p * log(p + 1e-10);
    }
    #pragma unroll
    for (int o = 16; o; o >>= 1) h += __shfl_xor_sync(0xffffffffu, h, o);
    if ((tid & 31) == 0) red[tid >> 5] = h;
    __syncthreads();
    if (tid == 0) {
        double t = 0.0;
        for (int i = 0; i < 32; i++) t += red[i];
        out[OFF_PERP] = (float)exp(-t);
        out[OFF_LOSS] = (float)(0.25 * g_loss / 16777216.0);
    }
}

// ---------------- launch ----------------
extern "C" void kernel_launch(void* const* d_in, const int* in_sizes, int n_in,
                              void* d_out, int out_size) {
    (void)in_sizes; (void)n_in; (void)out_size;
    const float* X      = (const float*)d_in[0];
    const float* dict   = (const float*)d_in[1];
    const float* counts = (const float*)d_in[2];
    float* out = (float*)d_out;

    cudaFuncSetAttribute(gemm_approx,
                         cudaFuncAttributeMaxDynamicSharedMemorySize, SM_TOTAL);

    compute_codewords<<<VOCAB, 128>>>(dict, counts);
    split_e<<<8192, 256>>>();
    split_x<<<32768, 256>>>(X);
    init_kernel<<<2048, 256>>>(dict, out);
    dim3 grid(M_ROWS / TM, VOCAB / (TN * NTPC));   // (256, 4)
    gemm_approx<<<grid, 512, SM_TOTAL>>>();
    rescore<<<2048, 256>>>(X);
    scatter_kernel<<<M_ROWS * 32 / 256, 256>>>(X, out);
    finalize_kernel<<<1, 1024>>>(counts, out);
}